// round 17
// baseline (speedup 1.0000x reference)
#include <cuda_runtime.h>
#include <cuda_fp16.h>
#include <math.h>
#include <stdint.h>

// Problem constants
#define BATCH_M   16384   // B*S
#define DIM_D     768
#define DIM_N     2304    // 3*D
#define NUM_T     10
#define RANK_R    16
#define SEG       (RANK_R * DIM_D)

// GEMM tiling: CTA 128x128, 8 warps (4M x 2N), tiled-global + bulk copy.
// Global tile = 128 rows x 32 fp16 = 8192 B, XOR-swizzled:
//   tile_off(r, c) = r*64 + (c ^ ((r>>1)&3))*16,  r in [0,128), c in [0,4)
#define BM 128
#define BN 128
#define KTILES    24               // K tiles of 32 fp16 (768/32)
#define TILEB     8192
#define SPT       12               // pipeline stages per output tile (BK=64)
#define GSTAGE    (4 * TILEB)      // 32768 per stage (A 16KB + B 16KB)
#define NSTAGE    3
#define SMEM_MB   (NSTAGE * GSTAGE)     // 98304
#define SMEM_TOTAL (SMEM_MB + 64)       // 98368 -> 2 CTAs/SM

// Persistent grid
#define NTILE_N   (DIM_N / BN)     // 18
#define NTILE_M   (BATCH_M / BM)   // 128
#define NTILES    (NTILE_N * NTILE_M)   // 2304
#define NPERS     304              // 2 CTAs x 152 SMs

// fused prep grid: [sumsq 160 | weff 864 | convert 3072]
#define NSUMSQ_BLOCKS 160
#define WEFF_DTILES  3             // 768 / 256
#define WEFF_EROWS   8
#define WEFF_ETILES  (DIM_N / WEFF_EROWS)            // 288
#define NWEFF_BLOCKS (WEFF_DTILES * WEFF_ETILES)     // 864
#define NCONV_BLOCKS 3072          // 3072 * 256 thr * 16 fp16 = X
#define CONV_BASE    (NSUMSQ_BLOCKS + NWEFF_BLOCKS)  // 1024

// Device scratch (no cudaMalloc allowed)
__device__ float g_part[NSUMSQ_BLOCKS];
__device__ int   g_ctr;            // sumsq completion counter (reset by GEMM)
__device__ __align__(16) unsigned short g_Xh[(size_t)BATCH_M * DIM_D]; // tiled
__device__ __align__(16) unsigned short g_Wh[(size_t)DIM_N * DIM_D];   // tiled

// ---------------------------------------------------------------------------
// Helpers
// ---------------------------------------------------------------------------
__device__ __forceinline__ uint32_t smem_u32(const void* p) {
    uint32_t a;
    asm("{ .reg .u64 t; cvta.to.shared.u64 t, %1; cvt.u32.u64 %0, t; }" : "=r"(a) : "l"(p));
    return a;
}
#define MBAR_INIT(addr, cnt) \
    asm volatile("mbarrier.init.shared.b64 [%0], %1;" :: "r"(addr), "r"(cnt) : "memory")
#define MBAR_EXPECT_TX(addr, tx) \
    asm volatile("mbarrier.arrive.expect_tx.shared.b64 _, [%0], %1;" :: "r"(addr), "r"(tx) : "memory")
#define BULK_G2S(dst, src, nbytes, mbar) \
    asm volatile("cp.async.bulk.shared::cluster.global.mbarrier::complete_tx::bytes " \
                 "[%0], [%1], %2, [%3];" \
                 :: "r"(dst), "l"(src), "r"(nbytes), "r"(mbar) : "memory")
#define MBAR_WAIT(addr, parity) do {                                             \
    uint32_t _m = (addr); uint32_t _p = (parity); uint32_t _d;                   \
    asm volatile("{ .reg .pred p; mbarrier.try_wait.parity.acquire.cta.shared::cta.b64 p, [%1], %2; selp.b32 %0,1,0,p; }" \
        : "=r"(_d) : "r"(_m), "r"(_p) : "memory");                               \
    while (!_d) {                                                                \
        asm volatile("{ .reg .pred p; mbarrier.try_wait.parity.acquire.cta.shared::cta.b64 p, [%1], %2, 0x989680; selp.b32 %0,1,0,p; }" \
            : "=r"(_d) : "r"(_m), "r"(_p) : "memory");                           \
    }                                                                            \
} while (0)

__device__ __forceinline__ void ldsm_x4(uint32_t* r, uint32_t addr) {
    asm volatile("ldmatrix.sync.aligned.m8n8.x4.shared.b16 {%0,%1,%2,%3}, [%4];"
        : "=r"(r[0]), "=r"(r[1]), "=r"(r[2]), "=r"(r[3]) : "r"(addr));
}
__device__ __forceinline__ void mma_fp16(float* c, const uint32_t* a,
                                         uint32_t b0, uint32_t b1) {
    asm volatile("mma.sync.aligned.m16n8k16.row.col.f32.f16.f16.f32 "
        "{%0,%1,%2,%3},{%4,%5,%6,%7},{%8,%9},{%0,%1,%2,%3};"
        : "+f"(c[0]), "+f"(c[1]), "+f"(c[2]), "+f"(c[3])
        : "r"(a[0]), "r"(a[1]), "r"(a[2]), "r"(a[3]), "r"(b0), "r"(b1));
}

// ---------------------------------------------------------------------------
// Kernel 1: fused prep. Grid = [sumsq 160 | weff 864 | convert 3072].
//   sumsq blocks publish partials + counter (release).
//   weff blocks acquire-spin on the counter (hidden under convert stream),
//   then build W_eff into the tiled layout.
//   convert blocks stream X -> fp16 tiled layout.
// ---------------------------------------------------------------------------
__global__ __launch_bounds__(256)
void k_prep(const float* __restrict__ x,
            const float* __restrict__ Aq, const float* __restrict__ Bq,
            const float* __restrict__ Av, const float* __restrict__ Bv,
            const float* __restrict__ qkvw,
            const float* __restrict__ logits, const float* __restrict__ alpha) {
    const int bid = blockIdx.x;
    const int tx  = threadIdx.x;

    if (bid < NSUMSQ_BLOCKS) {
        // ---- partial Frobenius sums: 4 blocks per (tensor,task) segment ----
        const int seg = bid >> 2;
        const int quarter = bid & 3;
        const float* base;
        switch (seg / NUM_T) {
            case 0:  base = Aq; break;
            case 1:  base = Bq; break;
            case 2:  base = Av; break;
            default: base = Bv; break;
        }
        const float4* p = (const float4*)(base + (seg % NUM_T) * SEG) + quarter * (SEG / 16);
        float s = 0.f;
        #pragma unroll
        for (int i = 0; i < 3; i++) {
            float4 v = __ldg(p + tx + i * 256);
            s += v.x * v.x + v.y * v.y + v.z * v.z + v.w * v.w;
        }
        #pragma unroll
        for (int o = 16; o > 0; o >>= 1)
            s += __shfl_xor_sync(0xFFFFFFFF, s, o);
        __shared__ float red[8];
        if ((tx & 31) == 0) red[tx >> 5] = s;
        __syncthreads();
        if (tx == 0) {
            float t = 0.f;
            #pragma unroll
            for (int i = 0; i < 8; i++) t += red[i];
            g_part[bid] = t;
            __threadfence();                    // release partial
            atomicAdd(&g_ctr, 1);
        }
        return;
    }

    if (bid >= CONV_BASE) {
        // ---- convert X: 16 fp16/thread, coalesced reads, tiled 32B writes ----
        int g = (bid - CONV_BASE) * 256 + tx;
        int m  = g / 48;                 // row
        int kq = g - m * 48;             // 16-fp16 quantum: k0 = kq*16
        const float* src = x + (size_t)m * DIM_D + kq * 16;
        float4 v0 = __ldg((const float4*)src);
        float4 v1 = __ldg((const float4*)src + 1);
        float4 v2 = __ldg((const float4*)src + 2);
        float4 v3 = __ldg((const float4*)src + 3);
        uint4 h0, h1;
        h0.x = (uint32_t)__half_as_ushort(__float2half(v0.x))
             | ((uint32_t)__half_as_ushort(__float2half(v0.y)) << 16);
        h0.y = (uint32_t)__half_as_ushort(__float2half(v0.z))
             | ((uint32_t)__half_as_ushort(__float2half(v0.w)) << 16);
        h0.z = (uint32_t)__half_as_ushort(__float2half(v1.x))
             | ((uint32_t)__half_as_ushort(__float2half(v1.y)) << 16);
        h0.w = (uint32_t)__half_as_ushort(__float2half(v1.z))
             | ((uint32_t)__half_as_ushort(__float2half(v1.w)) << 16);
        h1.x = (uint32_t)__half_as_ushort(__float2half(v2.x))
             | ((uint32_t)__half_as_ushort(__float2half(v2.y)) << 16);
        h1.y = (uint32_t)__half_as_ushort(__float2half(v2.z))
             | ((uint32_t)__half_as_ushort(__float2half(v2.w)) << 16);
        h1.z = (uint32_t)__half_as_ushort(__float2half(v3.x))
             | ((uint32_t)__half_as_ushort(__float2half(v3.y)) << 16);
        h1.w = (uint32_t)__half_as_ushort(__float2half(v3.z))
             | ((uint32_t)__half_as_ushort(__float2half(v3.w)) << 16);
        int mt = m >> 7, r = m & 127;
        int s  = kq >> 1, b2 = kq & 1;   // K-tile, 16-fp16 half within tile
        int swz = (r >> 1) & 3;
        char* tb = (char*)g_Xh + ((size_t)(mt * KTILES + s)) * TILEB + r * 64;
        *(uint4*)(tb + (((2 * b2)     ^ swz) * 16)) = h0;
        *(uint4*)(tb + (((2 * b2 + 1) ^ swz) * 16)) = h1;
        return;
    }

    // ---- W_eff: 8 e-rows x 256 d-cols per block, tiled output ----
    const int wb  = bid - NSUMSQ_BLOCKS;
    const int d   = (wb % WEFF_DTILES) * 256 + tx;
    const int e0  = (wb / WEFF_DTILES) * WEFF_EROWS;

    float acc[WEFF_EROWS];
    #pragma unroll
    for (int e = 0; e < WEFF_EROWS; e++) acc[e] = 0.f;

    bool is_q = (e0 < DIM_D);
    bool is_v = (e0 >= 2 * DIM_D);
    if (is_q || is_v) {
        __shared__ float sw[NUM_T];
        __shared__ __align__(16) float sB[NUM_T * RANK_R * WEFF_EROWS];  // [i][e]

        if (tx == 0) {
            // acquire: wait for all 160 sumsq partials
            while (*(volatile int*)&g_ctr < NSUMSQ_BLOCKS) { }
            __threadfence();
            float mx = -1e30f;
            float lg[NUM_T];
            #pragma unroll
            for (int t = 0; t < NUM_T; t++) { lg[t] = __ldg(logits + t); mx = fmaxf(mx, lg[t]); }
            float e[NUM_T], se = 0.f;
            #pragma unroll
            for (int t = 0; t < NUM_T; t++) { e[t] = expf(lg[t] - mx); se += e[t]; }
            #pragma unroll
            for (int t = 0; t < NUM_T; t++) {
                float coef = (e[t] / se) * __ldg(alpha + t);
                int sa  = is_q ? t : (20 + t);
                int sb2 = is_q ? (10 + t) : (30 + t);
                float ssa = g_part[4 * sa]  + g_part[4 * sa + 1]
                          + g_part[4 * sa + 2] + g_part[4 * sa + 3];
                float ssb = g_part[4 * sb2] + g_part[4 * sb2 + 1]
                          + g_part[4 * sb2 + 2] + g_part[4 * sb2 + 3];
                sw[t] = coef / (sqrtf(ssa) * sqrtf(ssb) + 1e-8f);
            }
        }
        __syncthreads();

        const float* Am = is_q ? Aq : Av;
        const float* Bm = is_q ? Bq : Bv;
        int el0 = is_q ? e0 : (e0 - 2 * DIM_D);
        for (int idx = tx; idx < NUM_T * RANK_R * WEFF_EROWS; idx += 256) {
            int i = idx >> 3, e = idx & 7;
            int t = i >> 4,  r = i & 15;
            sB[idx] = sw[t] * Bm[((size_t)t * DIM_D + el0 + e) * RANK_R + r];
        }
        __syncthreads();

        const float4* sB4 = (const float4*)sB;
        #pragma unroll 32
        for (int i = 0; i < NUM_T * RANK_R; i++) {
            float a = __ldg(Am + (size_t)i * DIM_D + d);
            float4 b0 = sB4[i * 2 + 0];
            float4 b1 = sB4[i * 2 + 1];
            acc[0] += a * b0.x;  acc[1] += a * b0.y;
            acc[2] += a * b0.z;  acc[3] += a * b0.w;
            acc[4] += a * b1.x;  acc[5] += a * b1.y;
            acc[6] += a * b1.z;  acc[7] += a * b1.w;
        }
    }
    // tiled store: nt = e0>>7, K-tile = d>>5, chunk = (d>>3)&3, byte = (d&7)*2
    {
        int nt = e0 >> 7;
        int s  = d >> 5;
        int c  = (d >> 3) & 3;
        int bo = (d & 7) * 2;
        char* tb = (char*)g_Wh + ((size_t)(nt * KTILES + s)) * TILEB;
        #pragma unroll
        for (int e = 0; e < WEFF_EROWS; e++) {
            float val = qkvw[(size_t)(e0 + e) * DIM_D + d] + acc[e];
            int r = (e0 + e) & 127;
            int swz = (r >> 1) & 3;
            *(unsigned short*)(tb + r * 64 + ((c ^ swz) * 16) + bo) =
                __half_as_ushort(__float2half(val));
        }
    }
}

// ---------------------------------------------------------------------------
// Kernel 2: PERSISTENT HMMA GEMM  out = Xh @ Wh^T + bias
//   304 CTAs (2/SM), continuous 3-stage bulk pipeline across tiles.
//   CTA 0 also resets the prep counter for the next graph replay.
// ---------------------------------------------------------------------------
__global__ __launch_bounds__(256, 2)
void k_gemm_mma(const float* __restrict__ bias, float* __restrict__ out) {
    extern __shared__ __align__(1024) char smem[];
    const uint32_t sb = smem_u32(smem);
    const uint32_t mb = sb + SMEM_MB;
    const int tid = threadIdx.x;
    const int lid = tid & 31;
    const int wid = tid >> 5;
    const int wm = wid & 3;          // 4 warps in M, 32 rows each
    const int wn = wid >> 2;         // 2 warps in N, 64 cols each
    const int cta = blockIdx.x;

    if (cta == 0 && tid == 0) g_ctr = 0;   // reset for next replay

    if (tid == 0) {
        #pragma unroll
        for (int j = 0; j < NSTAGE; j++) MBAR_INIT(mb + j * 8, 1);
    }
    __syncthreads();

    const int my_tiles = (NTILES - 1 - cta) / NPERS + 1;   // 7 or 8
    const int total_q  = my_tiles * SPT;

    auto issue = [&](int q) {
        int t  = cta + (q / SPT) * NPERS;
        int s  = q % SPT;
        int tm = t / NTILE_N;
        int tn = t - tm * NTILE_N;
        uint32_t m = mb + (uint32_t)(q % NSTAGE) * 8;
        uint32_t dst = sb + (uint32_t)(q % NSTAGE) * GSTAGE;
        const char* srcA = (const char*)g_Xh
            + ((size_t)tm * KTILES + (size_t)s * 2) * TILEB;
        const char* srcB = (const char*)g_Wh
            + ((size_t)tn * KTILES + (size_t)s * 2) * TILEB;
        MBAR_EXPECT_TX(m, GSTAGE);
        BULK_G2S(dst,             srcA, 2 * TILEB, m);
        BULK_G2S(dst + 2 * TILEB, srcB, 2 * TILEB, m);
    };

    if (tid == 0) { issue(0); if (total_q > 1) issue(1); }

    float acc[2][8][4];
    #pragma unroll
    for (int i = 0; i < 2; i++)
        #pragma unroll
        for (int j = 0; j < 8; j++)
            #pragma unroll
            for (int q2 = 0; q2 < 4; q2++) acc[i][j][q2] = 0.f;

    const int aRow  = wm * 32 + (lid & 15);
    const int aSwz  = ((lid & 15) >> 1) & 3;
    const int aCh   = lid >> 4;
    const int bRow  = (lid < 16) ? (lid & 7) : 8 + (lid & 7);
    const int bSwz  = (bRow >> 1) & 3;
    const int bCh   = (lid >> 3) & 1;

    for (int q = 0; q < total_q; q++) {
        MBAR_WAIT(mb + (uint32_t)(q % NSTAGE) * 8, (q / NSTAGE) & 1);
        __syncthreads();
        if (tid == 0 && q + 2 < total_q) issue(q + 2);

        uint32_t stage = sb + (uint32_t)(q % NSTAGE) * GSTAGE;
        #pragma unroll
        for (int kt = 0; kt < 2; kt++) {
            uint32_t bufA = stage + (uint32_t)kt * TILEB;
            uint32_t bufB = stage + 2 * TILEB + (uint32_t)kt * TILEB;
            #pragma unroll
            for (int kk = 0; kk < 2; kk++) {
                uint32_t cA = (uint32_t)(((kk * 2 + aCh) ^ aSwz) * 16);
                uint32_t ra[2][4];
                #pragma unroll
                for (int mt = 0; mt < 2; mt++)
                    ldsm_x4(ra[mt], bufA + (uint32_t)(aRow + mt * 16) * 64 + cA);
                uint32_t cB = (uint32_t)(((kk * 2 + bCh) ^ bSwz) * 16);
                #pragma unroll
                for (int half = 0; half < 2; half++) {
                    uint32_t rb[2][4];
                    #pragma unroll
                    for (int g = 0; g < 2; g++)
                        ldsm_x4(rb[g], bufB +
                            (uint32_t)(wn * 64 + (half * 2 + g) * 16 + bRow) * 64 + cB);
                    #pragma unroll
                    for (int mt = 0; mt < 2; mt++)
                        #pragma unroll
                        for (int n4 = 0; n4 < 4; n4++) {
                            uint32_t b0 = rb[n4 >> 1][(n4 & 1) * 2];
                            uint32_t b1 = rb[n4 >> 1][(n4 & 1) * 2 + 1];
                            mma_fp16(acc[mt][half * 4 + n4], ra[mt], b0, b1);
                        }
                }
            }
        }

        if ((q % SPT) == SPT - 1) {
            int t  = cta + (q / SPT) * NPERS;
            int tm = t / NTILE_N;
            int tn = t - tm * NTILE_N;
            const int r0 = tm * BM + wm * 32 + (lid >> 2);
            const int cb = tn * BN + wn * 64 + (lid & 3) * 2;
            #pragma unroll
            for (int nt = 0; nt < 8; nt++) {
                float2 bv = *(const float2*)(bias + cb + nt * 8);
                #pragma unroll
                for (int mt = 0; mt < 2; mt++) {
                    int r = r0 + mt * 16;
                    float2 v0 = make_float2(acc[mt][nt][0] + bv.x, acc[mt][nt][1] + bv.y);
                    float2 v1 = make_float2(acc[mt][nt][2] + bv.x, acc[mt][nt][3] + bv.y);
                    *(float2*)(out + (size_t)r * DIM_N + cb + nt * 8) = v0;
                    *(float2*)(out + (size_t)(r + 8) * DIM_N + cb + nt * 8) = v1;
                    acc[mt][nt][0] = 0.f; acc[mt][nt][1] = 0.f;
                    acc[mt][nt][2] = 0.f; acc[mt][nt][3] = 0.f;
                }
            }
        }
    }
}

// ---------------------------------------------------------------------------
// Launch
// ---------------------------------------------------------------------------
extern "C" void kernel_launch(void* const* d_in, const int* in_sizes, int n_in,
                              void* d_out, int out_size) {
    const float* x      = (const float*)d_in[0];
    const float* Aq     = (const float*)d_in[1];
    const float* Bq     = (const float*)d_in[2];
    const float* Av     = (const float*)d_in[3];
    const float* Bv     = (const float*)d_in[4];
    const float* qkvw   = (const float*)d_in[5];
    const float* qkvb   = (const float*)d_in[6];
    const float* logits = (const float*)d_in[7];
    const float* alpha  = (const float*)d_in[8];
    float* out = (float*)d_out;

    cudaFuncSetAttribute(k_gemm_mma, cudaFuncAttributeMaxDynamicSharedMemorySize, SMEM_TOTAL);

    k_prep    <<<NSUMSQ_BLOCKS + NWEFF_BLOCKS + NCONV_BLOCKS, 256>>>(
                  x, Aq, Bq, Av, Bv, qkvw, logits, alpha);
    k_gemm_mma<<<NPERS, 256, SMEM_TOTAL>>>(qkvb, out);
}